// round 10
// baseline (speedup 1.0000x reference)
#include <cuda_runtime.h>
#include <cuda_bf16.h>
#include <math.h>
#include <stdint.h>

// ---------------------------------------------------------------------------
// Swin block: B=32,H=W=56,C=192,NH=6,WS=7,SS=3,HD=32,N=49,MLP_H=768
// GEMMs + attention via mma.sync m16n8k16 bf16, ldmatrix, 3-stage cp.async.
// ---------------------------------------------------------------------------

#define Bn     32
#define Hh     56
#define Ww     56
#define Cc     192
#define NHh    6
#define WSs    7
#define SSs    3
#define HDd    32
#define Nn     49
#define MLPH   768
#define Ltok   (Hh*Ww)
#define TOT    (Bn*Ltok)          // 100352
#define NWIN   2048
#define SCALEF 0.17677669529663687f

// GEMM tiling: CTA 256x64, K-chunk 32, 3 stages, 8 warps (4M x 2N), warp 64x32.
#define BM    256
#define BN    64
#define BK    32
#define PITCH 40                    // bf16 units per smem row (80B)
#define A_ST  (BM*PITCH)            // 10240 bf16 = 20480 B per stage
#define B_ST  (BN*PITCH)            // 2560 bf16 = 5120 B... (40*64=2560)
#define SMEM_BYTES ((3*A_ST + 3*B_ST) * 2)   // 76800 B

typedef __nv_bfloat16 bf16;
typedef __nv_bfloat162 bf162;

// ------------------------- scratch (device globals) ------------------------
__device__ bf16  g_XW [TOT * Cc];
__device__ bf16  g_QKV[TOT * 3 * Cc];
__device__ bf16  g_ATT[TOT * Cc];
__device__ float g_XR [TOT * Cc];
__device__ bf16  g_XN2[TOT * Cc];
__device__ bf16  g_H  [TOT * MLPH];
__device__ bf16  g_Wq [576 * Cc];
__device__ bf16  g_Wp [Cc * Cc];
__device__ bf16  g_W1 [MLPH * Cc];
__device__ bf16  g_W2 [Cc * MLPH];
__device__ float g_BM [4 * NHh * 64 * 64];

// --------------------------- PTX helpers -----------------------------------
__device__ __forceinline__ uint32_t smem_u32(const void* p) {
    uint32_t a;
    asm("{ .reg .u64 t; cvta.to.shared.u64 t, %1; cvt.u32.u64 %0, t; }"
        : "=r"(a) : "l"(p));
    return a;
}

#define CP_ASYNC16(dst, src) \
    asm volatile("cp.async.cg.shared.global [%0], [%1], 16;" :: "r"(dst), "l"(src))
#define CP_COMMIT() asm volatile("cp.async.commit_group;")
#define CP_WAIT(n)  asm volatile("cp.async.wait_group %0;" :: "n"(n))

__device__ __forceinline__ void mma_bf16(float* c, const uint32_t* a, const uint32_t* b) {
    asm volatile(
        "mma.sync.aligned.m16n8k16.row.col.f32.bf16.bf16.f32 "
        "{%0,%1,%2,%3}, {%4,%5,%6,%7}, {%8,%9}, {%0,%1,%2,%3};"
        : "+f"(c[0]), "+f"(c[1]), "+f"(c[2]), "+f"(c[3])
        : "r"(a[0]), "r"(a[1]), "r"(a[2]), "r"(a[3]), "r"(b[0]), "r"(b[1]));
}

__device__ __forceinline__ void ldsm_x4(uint32_t* r, uint32_t addr) {
    asm volatile("ldmatrix.sync.aligned.m8n8.x4.shared.b16 {%0,%1,%2,%3}, [%4];"
                 : "=r"(r[0]), "=r"(r[1]), "=r"(r[2]), "=r"(r[3]) : "r"(addr));
}

__device__ __forceinline__ uint32_t packbf(float lo, float hi) {
    uint32_t r;
    asm("cvt.rn.bf16x2.f32 %0, %1, %2;" : "=r"(r) : "f"(hi), "f"(lo));
    return r;
}

// --------------------- token <-> (shifted window) mapping ------------------
__device__ __forceinline__ int win_to_tok(int t) {
    int win = t / Nn, r = t - win * Nn;
    int b = win >> 6, w_ = win & 63;
    int wh = w_ >> 3, ww = w_ & 7;
    int ih = r / WSs, iw = r - ih * WSs;
    int rr = wh * WSs + ih + SSs; if (rr >= Hh) rr -= Hh;
    int cc = ww * WSs + iw + SSs; if (cc >= Ww) cc -= Ww;
    return b * Ltok + rr * Ww + cc;
}

// ----------------------- weight conversion to bf16 --------------------------
__global__ void wconv_kernel(const float* __restrict__ qw, const float* __restrict__ pw,
                             const float* __restrict__ w1, const float* __restrict__ w2) {
    int i = blockIdx.x * blockDim.x + threadIdx.x;
    if (i < 576 * Cc)  g_Wq[i] = __float2bfloat16(qw[i]);
    if (i < Cc * Cc)   g_Wp[i] = __float2bfloat16(pw[i]);
    if (i < MLPH * Cc) g_W1[i] = __float2bfloat16(w1[i]);
    if (i < Cc * MLPH) g_W2[i] = __float2bfloat16(w2[i]);
}

// -------------------- bias + shift-mask table init -------------------------
__global__ void bm_init_kernel(const float* __restrict__ tbl) {
    int idx = blockIdx.x * blockDim.x + threadIdx.x;
    if (idx >= 4 * NHh * 64 * 64) return;
    int j = idx & 63, i = (idx >> 6) & 63;
    int hh = (idx >> 12) % NHh, wt = (idx >> 12) / NHh;
    float v;
    if (i < Nn && j < Nn) {
        int ih = i / 7, iw = i % 7, jh = j / 7, jw = j % 7;
        int ridx = (ih - jh + 6) * 13 + (iw - jw + 6);
        v = tbl[ridx * NHh + hh];
        int th = wt >> 1, tw = wt & 1;
        int li = (th ? (ih < 4 ? 1 : 2) : 0) * 3 + (tw ? (iw < 4 ? 1 : 2) : 0);
        int lj = (th ? (jh < 4 ? 1 : 2) : 0) * 3 + (tw ? (jw < 4 ? 1 : 2) : 0);
        if (li != lj) v -= 100.f;
    } else {
        v = -1e30f;
    }
    g_BM[idx] = v;
}

// --------------------------- LN kernels -------------------------------------
__global__ void ln1_gather_kernel(const float* __restrict__ x,
                                  const float* __restrict__ g,
                                  const float* __restrict__ bt) {
    int warp = (blockIdx.x * blockDim.x + threadIdx.x) >> 5;
    int lane = threadIdx.x & 31;
    if (warp >= TOT) return;
    const float* src = x + (size_t)win_to_tok(warp) * Cc;
    float v[6], s = 0.f, ss = 0.f;
#pragma unroll
    for (int k = 0; k < 6; k++) { v[k] = src[lane + k * 32]; s += v[k]; ss += v[k] * v[k]; }
#pragma unroll
    for (int o = 16; o; o >>= 1) {
        s  += __shfl_xor_sync(0xffffffffu, s, o);
        ss += __shfl_xor_sync(0xffffffffu, ss, o);
    }
    float mu = s * (1.f / Cc);
    float rstd = rsqrtf(ss * (1.f / Cc) - mu * mu + 1e-5f);
    bf16* dst = g_XW + (size_t)warp * Cc;
#pragma unroll
    for (int k = 0; k < 6; k++) {
        int c = lane + k * 32;
        dst[c] = __float2bfloat16((v[k] - mu) * rstd * g[c] + bt[c]);
    }
}

__global__ void ln2_kernel(const float* __restrict__ g,
                           const float* __restrict__ bt) {
    int warp = (blockIdx.x * blockDim.x + threadIdx.x) >> 5;
    int lane = threadIdx.x & 31;
    if (warp >= TOT) return;
    const float* src = g_XR + (size_t)warp * Cc;
    float v[6], s = 0.f, ss = 0.f;
#pragma unroll
    for (int k = 0; k < 6; k++) { v[k] = src[lane + k * 32]; s += v[k]; ss += v[k] * v[k]; }
#pragma unroll
    for (int o = 16; o; o >>= 1) {
        s  += __shfl_xor_sync(0xffffffffu, s, o);
        ss += __shfl_xor_sync(0xffffffffu, ss, o);
    }
    float mu = s * (1.f / Cc);
    float rstd = rsqrtf(ss * (1.f / Cc) - mu * mu + 1e-5f);
    bf16* dst = g_XN2 + (size_t)warp * Cc;
#pragma unroll
    for (int k = 0; k < 6; k++) {
        int c = lane + k * 32;
        dst[c] = __float2bfloat16((v[k] - mu) * rstd * g[c] + bt[c]);
    }
}

// --------------------------- bf16 mma GEMM ----------------------------------
// C[M,Nd] = A[M,KK] * W[Nd,KK]^T.  CTA 256x64, 8 warps 4(M)x2(N), warp 64x32.
// BK=32, 3-stage cp.async, one __syncthreads per chunk, ldmatrix loads.
template <int EPI, int KK>
__global__ __launch_bounds__(256)
void gemm_mma(const bf16* __restrict__ A, const bf16* __restrict__ W,
              const float* __restrict__ bias, const float* __restrict__ res,
              void* __restrict__ outp, int Nd) {
    constexpr int NC = KK / BK;
    extern __shared__ __align__(16) bf16 smem[];
    uint32_t a_st[3], b_st[3];
#pragma unroll
    for (int s = 0; s < 3; ++s) {
        a_st[s] = smem_u32(smem + s * A_ST);
        b_st[s] = smem_u32(smem + 3 * A_ST + s * B_ST);
    }

    const int tid = threadIdx.x;
    const int wid = tid >> 5;
    const int lane = tid & 31;
    const int gr = lane >> 2, gc = lane & 3;
    const int wm = wid >> 1;          // 0..3 (64 rows each)
    const int wn = wid & 1;           // 0..1 (32 cols each)
    const int mbase = blockIdx.x * BM;
    const int nbase = blockIdx.y * BN;

    const bf16* Ab = A + (size_t)mbase * KK;
    const bf16* Wb = W + (size_t)nbase * KK;

    // ldmatrix per-lane addressing
    const int rA = wm * 64 + (lane & 15);
    const int cA = (lane >> 4) << 3;
    const int rB = wn * 32 + (lane & 7) + ((lane >> 4) << 3);
    const int cB = ((lane >> 3) & 1) << 3;

    float acc[4][4][4];
#pragma unroll
    for (int i = 0; i < 4; i++)
#pragma unroll
        for (int j = 0; j < 4; j++)
#pragma unroll
            for (int k = 0; k < 4; k++) acc[i][j][k] = 0.f;

    // loader lambda-ish macro: stage s <- chunk c
#define LOAD_CHUNK(sidx, cidx)                                                  \
    do {                                                                        \
        const int koff = (cidx) * BK;                                           \
        _Pragma("unroll")                                                       \
        for (int i = tid; i < BM * 4; i += 256) {                               \
            int row = i >> 2, seg = i & 3;                                      \
            CP_ASYNC16(a_st[sidx] + (uint32_t)(row * 80 + seg * 16),            \
                       Ab + (size_t)row * KK + koff + seg * 8);                 \
        }                                                                       \
        _Pragma("unroll")                                                       \
        for (int i = tid; i < BN * 4; i += 256) {                               \
            int row = i >> 2, seg = i & 3;                                      \
            CP_ASYNC16(b_st[sidx] + (uint32_t)(row * 80 + seg * 16),            \
                       Wb + (size_t)row * KK + koff + seg * 8);                 \
        }                                                                       \
        CP_COMMIT();                                                            \
    } while (0)

    LOAD_CHUNK(0, 0);
    LOAD_CHUNK(1, 1);

    int sc = 0;   // stage of current chunk
    for (int c = 0; c < NC; ++c) {
        CP_WAIT(1);
        __syncthreads();
        if (c + 2 < NC) {
            int sn = sc + 2; if (sn >= 3) sn -= 3;
            LOAD_CHUNK(sn, c + 2);
        }
        const uint32_t ab = a_st[sc];
        const uint32_t bb = b_st[sc];
#pragma unroll
        for (int ks = 0; ks < 2; ++ks) {
            const int kk = ks * 16;
            uint32_t af[4][4], bq[2][4];
            ldsm_x4(bq[0], bb + (uint32_t)(rB * PITCH + kk + cB) * 2);
            ldsm_x4(bq[1], bb + (uint32_t)((rB + 16) * PITCH + kk + cB) * 2);
#pragma unroll
            for (int mt = 0; mt < 4; ++mt)
                ldsm_x4(af[mt], ab + (uint32_t)((rA + mt * 16) * PITCH + kk + cA) * 2);
#pragma unroll
            for (int mt = 0; mt < 4; ++mt) {
                mma_bf16(acc[mt][0], af[mt], &bq[0][0]);
                mma_bf16(acc[mt][1], af[mt], &bq[0][2]);
                mma_bf16(acc[mt][2], af[mt], &bq[1][0]);
                mma_bf16(acc[mt][3], af[mt], &bq[1][2]);
            }
        }
        if (++sc == 3) sc = 0;
    }
#undef LOAD_CHUNK

    // ----------------------- fused epilogue ---------------------------------
#pragma unroll
    for (int mt = 0; mt < 4; ++mt) {
#pragma unroll
        for (int half = 0; half < 2; ++half) {
            int row = mbase + wm * 64 + mt * 16 + gr + half * 8;
            int orow = row;
            if (EPI == 1) orow = win_to_tok(row);
#pragma unroll
            for (int nt = 0; nt < 4; ++nt) {
                int col = nbase + wn * 32 + nt * 8 + gc * 2;
                float v0 = acc[mt][nt][half * 2 + 0];
                float v1 = acc[mt][nt][half * 2 + 1];
                if (EPI == 0) {
                    *(uint32_t*)((bf16*)outp + (size_t)orow * Nd + col) = packbf(v0, v1);
                } else if (EPI == 1) {
                    const float* rp = res + (size_t)orow * Nd + col;
                    float2 o = make_float2(v0 + bias[col] + rp[0],
                                           v1 + bias[col + 1] + rp[1]);
                    *(float2*)((float*)outp + (size_t)orow * Nd + col) = o;
                } else if (EPI == 2) {
                    float a0 = v0 + bias[col], a1 = v1 + bias[col + 1];
                    const float kc = 0.70710678118654752f;
                    *(uint32_t*)((bf16*)outp + (size_t)orow * Nd + col) =
                        packbf(0.5f * a0 * (1.f + erff(a0 * kc)),
                               0.5f * a1 * (1.f + erff(a1 * kc)));
                } else {
                    const float* rp = res + (size_t)row * Nd + col;
                    float2 o = make_float2(v0 + bias[col] + rp[0],
                                           v1 + bias[col + 1] + rp[1]);
                    *(float2*)((float*)outp + (size_t)orow * Nd + col) = o;
                }
            }
        }
    }
}

// --------------------------- mma attention ----------------------------------
#define ATTN_SMEM_BYTES (6 * 3712 * 4)   // 89088

__global__ __launch_bounds__(384, 1)
void attn_mma_kernel() {
    extern __shared__ uint32_t sm32[];
    const int tid = threadIdx.x;
    const int win = blockIdx.x;
    const int h = tid >> 6;
    const int t2 = tid & 63;

    uint32_t* Qs = sm32 + h * 3712;
    uint32_t* Ks = Qs + 1280;
    uint32_t* Vt = Ks + 1280;

    for (int i = t2; i < 3712; i += 64) Qs[i] = 0;
    __syncthreads();

    const uint32_t* qkv = (const uint32_t*)g_QKV + (size_t)win * Nn * 288;
    bf16* vtb = (bf16*)Vt;
    for (int i = t2; i < Nn * 16; i += 64) {
        int row = i >> 4, wd = i & 15;
        const uint32_t* tp = qkv + row * 288 + h * 16 + wd;
        Qs[row * 20 + wd] = tp[0];
        Ks[row * 20 + wd] = tp[96];
        uint32_t vv = tp[192];
        bf162 v2 = *(bf162*)&vv;
        vtb[(2 * wd) * 72 + row]     = v2.x;
        vtb[(2 * wd + 1) * 72 + row] = v2.y;
    }
    __syncthreads();

    const int w = tid >> 5;
    const int lane = tid & 31;
    const int gr = lane >> 2, gc = lane & 3;
    const int qb = (w & 1) * 32;
    const int wh = (win & 63) >> 3, ww = win & 7;
    const int wt = ((wh == 7) ? 2 : 0) + ((ww == 7) ? 1 : 0);
    const float* bmp = g_BM + ((size_t)(wt * NHh + h) << 12);

    float sacc[2][8][4];
#pragma unroll
    for (int a = 0; a < 2; a++)
#pragma unroll
        for (int b = 0; b < 8; b++)
#pragma unroll
            for (int cse = 0; cse < 4; cse++) sacc[a][b][cse] = 0.f;

#pragma unroll
    for (int kst = 0; kst < 2; ++kst) {
        uint32_t af[2][4], bfr[8][2];
#pragma unroll
        for (int mt = 0; mt < 2; ++mt) {
            int r = qb + mt * 16 + gr;
            af[mt][0] = Qs[r * 20 + kst * 8 + gc];
            af[mt][1] = Qs[(r + 8) * 20 + kst * 8 + gc];
            af[mt][2] = Qs[r * 20 + kst * 8 + gc + 4];
            af[mt][3] = Qs[(r + 8) * 20 + kst * 8 + gc + 4];
        }
#pragma unroll
        for (int nt = 0; nt < 8; ++nt) {
            int j = nt * 8 + gr;
            bfr[nt][0] = Ks[j * 20 + kst * 8 + gc];
            bfr[nt][1] = Ks[j * 20 + kst * 8 + gc + 4];
        }
#pragma unroll
        for (int mt = 0; mt < 2; ++mt)
#pragma unroll
            for (int nt = 0; nt < 8; ++nt)
                mma_bf16(sacc[mt][nt], af[mt], bfr[nt]);
    }

    float invr[2][2];
#pragma unroll
    for (int mt = 0; mt < 2; ++mt) {
#pragma unroll
        for (int hf = 0; hf < 2; ++hf) {
            int row = qb + mt * 16 + gr + hf * 8;
            const float* bmr = bmp + row * 64 + 2 * gc;
            float v[8][2], mx = -3e38f;
#pragma unroll
            for (int nt = 0; nt < 8; ++nt) {
                float2 bm2 = *(const float2*)(bmr + nt * 8);
                v[nt][0] = sacc[mt][nt][hf * 2 + 0] * SCALEF + bm2.x;
                v[nt][1] = sacc[mt][nt][hf * 2 + 1] * SCALEF + bm2.y;
                mx = fmaxf(mx, fmaxf(v[nt][0], v[nt][1]));
            }
            mx = fmaxf(mx, __shfl_xor_sync(0xffffffffu, mx, 1));
            mx = fmaxf(mx, __shfl_xor_sync(0xffffffffu, mx, 2));
            float sum = 0.f;
#pragma unroll
            for (int nt = 0; nt < 8; ++nt) {
                float e0 = __expf(v[nt][0] - mx);
                float e1 = __expf(v[nt][1] - mx);
                sacc[mt][nt][hf * 2 + 0] = e0;
                sacc[mt][nt][hf * 2 + 1] = e1;
                sum += e0 + e1;
            }
            sum += __shfl_xor_sync(0xffffffffu, sum, 1);
            sum += __shfl_xor_sync(0xffffffffu, sum, 2);
            invr[mt][hf] = 1.f / sum;
        }
    }

    float o[2][4][4];
#pragma unroll
    for (int a = 0; a < 2; a++)
#pragma unroll
        for (int b = 0; b < 4; b++)
#pragma unroll
            for (int cse = 0; cse < 4; cse++) o[a][b][cse] = 0.f;

#pragma unroll
    for (int k2 = 0; k2 < 4; ++k2) {
        uint32_t pf[2][4];
#pragma unroll
        for (int mt = 0; mt < 2; ++mt) {
            pf[mt][0] = packbf(sacc[mt][2 * k2][0],     sacc[mt][2 * k2][1]);
            pf[mt][1] = packbf(sacc[mt][2 * k2][2],     sacc[mt][2 * k2][3]);
            pf[mt][2] = packbf(sacc[mt][2 * k2 + 1][0], sacc[mt][2 * k2 + 1][1]);
            pf[mt][3] = packbf(sacc[mt][2 * k2 + 1][2], sacc[mt][2 * k2 + 1][3]);
        }
#pragma unroll
        for (int ntd = 0; ntd < 4; ++ntd) {
            uint32_t bv[2];
            int d = ntd * 8 + gr;
            bv[0] = Vt[d * 36 + k2 * 8 + gc];
            bv[1] = Vt[d * 36 + k2 * 8 + gc + 4];
            mma_bf16(o[0][ntd], pf[0], bv);
            mma_bf16(o[1][ntd], pf[1], bv);
        }
    }

#pragma unroll
    for (int mt = 0; mt < 2; ++mt) {
#pragma unroll
        for (int hf = 0; hf < 2; ++hf) {
            int row = qb + mt * 16 + gr + hf * 8;
            if (row < Nn) {
                float iv = invr[mt][hf];
                bf16* op = g_ATT + ((size_t)(win * Nn + row)) * Cc + h * HDd;
#pragma unroll
                for (int ntd = 0; ntd < 4; ++ntd) {
                    *(uint32_t*)(op + ntd * 8 + 2 * gc) =
                        packbf(o[mt][ntd][hf * 2] * iv, o[mt][ntd][hf * 2 + 1] * iv);
                }
            }
        }
    }
}

// --------------------------- launch ------------------------------------------
extern "C" void kernel_launch(void* const* d_in, const int* in_sizes, int n_in,
                              void* d_out, int out_size) {
    const float* x        = (const float*)d_in[0];
    const float* norm1_g  = (const float*)d_in[1];
    const float* norm1_b  = (const float*)d_in[2];
    const float* qkv_w    = (const float*)d_in[3];
    const float* rel_bias = (const float*)d_in[4];
    const float* proj_w   = (const float*)d_in[5];
    const float* proj_b   = (const float*)d_in[6];
    const float* norm2_g  = (const float*)d_in[7];
    const float* norm2_b  = (const float*)d_in[8];
    const float* fc1_w    = (const float*)d_in[9];
    const float* fc1_b    = (const float*)d_in[10];
    const float* fc2_w    = (const float*)d_in[11];
    const float* fc2_b    = (const float*)d_in[12];
    float* out = (float*)d_out;

    bf16 *XW, *QKV, *ATT, *XN2, *Hb, *Wq, *Wp, *W1, *W2;
    float *XR;
    cudaGetSymbolAddress((void**)&XW,  g_XW);
    cudaGetSymbolAddress((void**)&QKV, g_QKV);
    cudaGetSymbolAddress((void**)&ATT, g_ATT);
    cudaGetSymbolAddress((void**)&XR,  g_XR);
    cudaGetSymbolAddress((void**)&XN2, g_XN2);
    cudaGetSymbolAddress((void**)&Hb,  g_H);
    cudaGetSymbolAddress((void**)&Wq,  g_Wq);
    cudaGetSymbolAddress((void**)&Wp,  g_Wp);
    cudaGetSymbolAddress((void**)&W1,  g_W1);
    cudaGetSymbolAddress((void**)&W2,  g_W2);

    cudaFuncSetAttribute(gemm_mma<0, 192>, cudaFuncAttributeMaxDynamicSharedMemorySize, SMEM_BYTES);
    cudaFuncSetAttribute(gemm_mma<1, 192>, cudaFuncAttributeMaxDynamicSharedMemorySize, SMEM_BYTES);
    cudaFuncSetAttribute(gemm_mma<2, 192>, cudaFuncAttributeMaxDynamicSharedMemorySize, SMEM_BYTES);
    cudaFuncSetAttribute(gemm_mma<3, 768>, cudaFuncAttributeMaxDynamicSharedMemorySize, SMEM_BYTES);
    cudaFuncSetAttribute(attn_mma_kernel, cudaFuncAttributeMaxDynamicSharedMemorySize, ATTN_SMEM_BYTES);

    // 0. weights -> bf16; bias+mask table
    wconv_kernel<<<(MLPH * Cc + 255) / 256, 256>>>(qkv_w, proj_w, fc1_w, fc2_w);
    bm_init_kernel<<<(4 * NHh * 64 * 64 + 255) / 256, 256>>>(rel_bias);
    // 1. LN1 + cyclic shift + window partition -> XW (bf16)
    ln1_gather_kernel<<<TOT / 8, 256>>>(x, norm1_g, norm1_b);
    // 2. QKV gemm -> QKV (bf16)
    gemm_mma<0, 192><<<dim3(TOT / BM, 576 / BN), 256, SMEM_BYTES>>>(XW, Wq, nullptr, nullptr, QKV, 3 * Cc);
    // 3. windowed attention (mma) -> ATT (bf16)
    attn_mma_kernel<<<NWIN, 384, ATTN_SMEM_BYTES>>>();
    // 4. proj + bias + reverse scatter + residual -> XR (fp32)
    gemm_mma<1, 192><<<dim3(TOT / BM, Cc / BN), 256, SMEM_BYTES>>>(ATT, Wp, proj_b, x, XR, Cc);
    // 5. LN2 -> XN2 (bf16)
    ln2_kernel<<<TOT / 8, 256>>>(norm2_g, norm2_b);
    // 6. FC1 + bias + exact GELU -> H (bf16)
    gemm_mma<2, 192><<<dim3(TOT / BM, MLPH / BN), 256, SMEM_BYTES>>>(XN2, W1, fc1_b, nullptr, Hb, MLPH);
    // 7. FC2 + bias + residual(XR) -> out (fp32)
    gemm_mma<3, 768><<<dim3(TOT / BM, Cc / BN), 256, SMEM_BYTES>>>(Hb, W2, fc2_b, XR, out, Cc);
}